// round 7
// baseline (speedup 1.0000x reference)
#include <cuda_runtime.h>
#include <cuda_bf16.h>

// BSplineActivation: y = sum_i B_i^3(clip(x,-1,1)) * c_i, uniform 12-knot
// grid, 8 coefficients. Per interval j (0..10) the spline is one cubic;
// bases+coefficients folded into an 11-entry cubic table re-centered at
// t=0.5 (magic-number floor gives index bits + fractional offset s with only
// FADD/LOP3, no F2I/I2F).
//
// R7 changes:
//  - Table is 8-way bank-replicated (sP[j*8 + lane%8], 88 float4 = 1.4KB):
//    one conflict-free LDS.128 per element (entry at j*128 + c*16 -> lane in
//    an 8-lane phase touches banks 4c..4c+3, disjoint). Was 2x LDS.64.
//  - Input LDG.128s are issued BEFORE the table build so the coef/grid load
//    latency of the CTA prologue overlaps the streaming loads.

#define THREADS 256
#define VPT 4              // float4 per thread
#define MAGIC 12582912.0f  // 1.5 * 2^23

__global__ void __launch_bounds__(THREADS, 5)
bspline_act_kernel(const float* __restrict__ x,
                   const float* __restrict__ grid,
                   const float* __restrict__ coef,
                   float* __restrict__ out,
                   int n4)
{
    __shared__ float4 sP[88];     // [j*8 + c], c = lane%8 replication
    __shared__ float  sInvH, sC;

    const int tid = threadIdx.x;

    const float4* __restrict__ x4 = (const float4*)x;
    float4* __restrict__ o4 = (float4*)out;

    const int base = blockIdx.x * (THREADS * VPT) + tid;

    // ---- Issue streaming input loads FIRST (overlap prologue latency) ----
    float4 v[VPT];
    #pragma unroll
    for (int q = 0; q < VPT; q++) {
        int i = base + q * THREADS;
        if (i < n4) v[q] = x4[i];
    }

    // ---- Table build (88 threads, one replicated entry each) ----
    if (tid < 88) {
        int j = tid >> 3;   // 0..10
        int i0 = j - 3, i1 = j - 2, i2 = j - 1, i3 = j;
        float c0 = (i0 >= 0) ? __ldg(&coef[i0]) : 0.0f;   // i0 <= 7 always
        float c1 = (i1 >= 0) ? __ldg(&coef[i1]) : 0.0f;
        float c2 = (i2 >= 0 && i2 < 8) ? __ldg(&coef[i2]) : 0.0f;
        float c3 = (i3 < 8) ? __ldg(&coef[i3]) : 0.0f;
        // Cubic in t: P0..P3 (uniform B-spline bases folded with coefs)
        float P0 = (c0 + 4.0f * c1 + c2) * (1.0f / 6.0f);
        float P1 = (c2 - c0) * 0.5f;
        float P2 = (c0 - 2.0f * c1 + c2) * 0.5f;
        float P3 = (c3 - c0 + 3.0f * (c1 - c2)) * (1.0f / 6.0f);
        // Re-center at t = s + 0.5
        float4 Q;
        Q.x = P0 + 0.5f * P1 + 0.25f * P2 + 0.125f * P3;
        Q.y = P1 + P2 + 0.75f * P3;
        Q.z = P2 + 1.5f * P3;
        Q.w = P3;
        sP[tid] = Q;
        if (tid == 0) {
            float g0   = __ldg(&grid[0]);
            float g11  = __ldg(&grid[11]);
            float invh = 11.0f / (g11 - g0);
            sInvH = invh;
            sC    = -g0 * invh - 0.5f;
        }
    }
    __syncthreads();

    const float invh = sInvH;
    const float cadd = sC;
    const unsigned coff = (tid & 7u) << 4;   // this lane's 16B replica column

    #pragma unroll
    for (int q = 0; q < VPT; q++) {
        float4 r;
        #pragma unroll
        for (int k = 0; k < 4; k++) {
            float xv = (k == 0) ? v[q].x : (k == 1) ? v[q].y
                     : (k == 2) ? v[q].z : v[q].w;
            float xc = fminf(fmaxf(xv, -1.0f), 1.0f);
            float u  = fmaf(xc, invh, cadd);   // in [0.417, 9.583]
            float f  = u + MAGIC;
            float jf = f - MAGIC;              // round(u)
            float s  = u - jf;                 // in [-0.5, 0.5]
            // byte offset = j*128 + c*16, j = low bits of f's mantissa
            unsigned off = ((__float_as_uint(f) << 7) & (15u << 7)) | coff;
            float4 Q = *(const float4*)((const char*)sP + off);
            float y  = fmaf(fmaf(fmaf(Q.w, s, Q.z), s, Q.y), s, Q.x);
            if (k == 0) r.x = y; else if (k == 1) r.y = y;
            else if (k == 2) r.z = y; else r.w = y;
        }
        int i = base + q * THREADS;
        if (i < n4) o4[i] = r;
    }
}

// Scalar tail kernel for n % 4 != 0 (not hit for 2048x4096).
__global__ void bspline_tail_kernel(const float* __restrict__ x,
                                    const float* __restrict__ grid,
                                    const float* __restrict__ coef,
                                    float* __restrict__ out,
                                    int start, int n)
{
    int idx = start + threadIdx.x;
    if (idx >= n) return;
    float g0  = grid[0];
    float invh = 11.0f / (grid[11] - g0);
    float xc = fminf(fmaxf(x[idx], -1.0f), 1.0f);
    float u  = (xc - g0) * invh;
    int   j  = min(max((int)u, 0), 10);
    float t  = u - (float)j;
    int i0 = j - 3, i1 = j - 2, i2 = j - 1, i3 = j;
    float c0 = (i0 >= 0 && i0 < 8) ? coef[i0] : 0.0f;
    float c1 = (i1 >= 0 && i1 < 8) ? coef[i1] : 0.0f;
    float c2 = (i2 >= 0 && i2 < 8) ? coef[i2] : 0.0f;
    float c3 = (i3 >= 0 && i3 < 8) ? coef[i3] : 0.0f;
    float p0 = (c0 + 4.0f * c1 + c2) * (1.0f / 6.0f);
    float p1 = (c2 - c0) * 0.5f;
    float p2 = (c0 - 2.0f * c1 + c2) * 0.5f;
    float p3 = (c3 - c0 + 3.0f * (c1 - c2)) * (1.0f / 6.0f);
    out[idx] = fmaf(fmaf(fmaf(p3, t, p2), t, p1), t, p0);
}

extern "C" void kernel_launch(void* const* d_in, const int* in_sizes, int n_in,
                              void* d_out, int out_size)
{
    const float* x    = (const float*)d_in[0];   // [2048*4096] fp32
    const float* grid = (const float*)d_in[1];   // [12] fp32
    const float* coef = (const float*)d_in[2];   // [8] fp32
    float* out = (float*)d_out;

    const int n  = in_sizes[0];
    const int n4 = n >> 2;

    int per_block = THREADS * VPT;
    int blocks = (n4 + per_block - 1) / per_block;
    if (blocks < 1) blocks = 1;

    bspline_act_kernel<<<blocks, THREADS>>>(x, grid, coef, out, n4);

    const int rem = n & 3;
    if (rem) {
        bspline_tail_kernel<<<1, 4>>>(x, grid, coef, out, n4 << 2, n);
    }
}

// round 8
// speedup vs baseline: 1.0201x; 1.0201x over previous
#include <cuda_runtime.h>
#include <cuda_bf16.h>

// BSplineActivation: y = sum_i B_i^3(clip(x,-1,1)) * c_i, uniform 12-knot
// grid, 8 coefficients. Per interval j (0..10) the spline is one cubic;
// bases+coefficients folded into an 11-entry cubic table re-centered at
// t=0.5 (magic-number round gives index bits + fractional offset s with only
// FADD/LOP3, no F2I/I2F).
//
// R8: ZERO shared memory. The 11-entry table lives in registers across the
// warp (lane l holds Q(l)); the per-element gather is 4x SHFL.IDX, which is
// served by the shuffle unit -> the L1TEX pipe carries ONLY the pure
// LDG/STG stream (memcpy-like). No __syncthreads, no smem handshake.

#define THREADS 256
#define VPT 4              // float4 per thread
#define MAGIC 12582912.0f  // 1.5 * 2^23

__global__ void __launch_bounds__(THREADS, 5)
bspline_act_kernel(const float* __restrict__ x,
                   const float* __restrict__ grid,
                   const float* __restrict__ coef,
                   float* __restrict__ out,
                   int n4)
{
    const int tid  = threadIdx.x;
    const int lane = tid & 31;

    const float4* __restrict__ x4 = (const float4*)x;
    float4* __restrict__ o4 = (float4*)out;

    const int base = blockIdx.x * (THREADS * VPT) + tid;

    // ---- Issue streaming input loads FIRST (overlap table-build latency) ----
    float4 v[VPT];
    #pragma unroll
    for (int q = 0; q < VPT; q++) {
        int i = base + q * THREADS;
        if (i < n4) v[q] = x4[i];
    }

    // ---- Per-lane table build: lane l holds cubic Q(l) for interval l ----
    // (lanes 11..31 compute a clamped entry; never selected since j <= 10)
    float q0, q1, q2, q3;
    {
        int j = lane < 11 ? lane : 10;
        int i0 = j - 3, i1 = j - 2, i2 = j - 1, i3 = j;
        float c0 = (i0 >= 0) ? __ldg(&coef[i0]) : 0.0f;   // i0 <= 7 always
        float c1 = (i1 >= 0) ? __ldg(&coef[i1]) : 0.0f;
        float c2 = (i2 >= 0 && i2 < 8) ? __ldg(&coef[i2]) : 0.0f;
        float c3 = (i3 < 8) ? __ldg(&coef[i3]) : 0.0f;
        // Cubic in t: P0..P3 (uniform B-spline bases folded with coefs)
        float P0 = (c0 + 4.0f * c1 + c2) * (1.0f / 6.0f);
        float P1 = (c2 - c0) * 0.5f;
        float P2 = (c0 - 2.0f * c1 + c2) * 0.5f;
        float P3 = (c3 - c0 + 3.0f * (c1 - c2)) * (1.0f / 6.0f);
        // Re-center at t = s + 0.5, s in [-0.5, 0.5]
        q0 = P0 + 0.5f * P1 + 0.25f * P2 + 0.125f * P3;
        q1 = P1 + P2 + 0.75f * P3;
        q2 = P2 + 1.5f * P3;
        q3 = P3;
    }
    const float g0   = __ldg(&grid[0]);
    const float g11  = __ldg(&grid[11]);
    const float invh = 11.0f / (g11 - g0);
    const float cadd = -g0 * invh - 0.5f;

    #pragma unroll
    for (int q = 0; q < VPT; q++) {
        float4 r;
        #pragma unroll
        for (int k = 0; k < 4; k++) {
            float xv = (k == 0) ? v[q].x : (k == 1) ? v[q].y
                     : (k == 2) ? v[q].z : v[q].w;
            float xc = fminf(fmaxf(xv, -1.0f), 1.0f);
            float u  = fmaf(xc, invh, cadd);   // in [0.417, 9.583]
            float f  = u + MAGIC;
            float jf = f - MAGIC;              // round(u) = original floor
            float s  = u - jf;                 // in [-0.5, 0.5]
            int   j  = (int)(__float_as_uint(f) & 15u);
            // Warp-register table gather: 4 independent SHFL.IDX
            float Q0 = __shfl_sync(0xffffffffu, q0, j);
            float Q1 = __shfl_sync(0xffffffffu, q1, j);
            float Q2 = __shfl_sync(0xffffffffu, q2, j);
            float Q3 = __shfl_sync(0xffffffffu, q3, j);
            float y  = fmaf(fmaf(fmaf(Q3, s, Q2), s, Q1), s, Q0);
            if (k == 0) r.x = y; else if (k == 1) r.y = y;
            else if (k == 2) r.z = y; else r.w = y;
        }
        int i = base + q * THREADS;
        if (i < n4) o4[i] = r;
    }
}

// Scalar tail kernel for n % 4 != 0 (not hit for 2048x4096).
__global__ void bspline_tail_kernel(const float* __restrict__ x,
                                    const float* __restrict__ grid,
                                    const float* __restrict__ coef,
                                    float* __restrict__ out,
                                    int start, int n)
{
    int idx = start + threadIdx.x;
    if (idx >= n) return;
    float g0  = grid[0];
    float invh = 11.0f / (grid[11] - g0);
    float xc = fminf(fmaxf(x[idx], -1.0f), 1.0f);
    float u  = (xc - g0) * invh;
    int   j  = min(max((int)u, 0), 10);
    float t  = u - (float)j;
    int i0 = j - 3, i1 = j - 2, i2 = j - 1, i3 = j;
    float c0 = (i0 >= 0 && i0 < 8) ? coef[i0] : 0.0f;
    float c1 = (i1 >= 0 && i1 < 8) ? coef[i1] : 0.0f;
    float c2 = (i2 >= 0 && i2 < 8) ? coef[i2] : 0.0f;
    float c3 = (i3 >= 0 && i3 < 8) ? coef[i3] : 0.0f;
    float p0 = (c0 + 4.0f * c1 + c2) * (1.0f / 6.0f);
    float p1 = (c2 - c0) * 0.5f;
    float p2 = (c0 - 2.0f * c1 + c2) * 0.5f;
    float p3 = (c3 - c0 + 3.0f * (c1 - c2)) * (1.0f / 6.0f);
    out[idx] = fmaf(fmaf(fmaf(p3, t, p2), t, p1), t, p0);
}

extern "C" void kernel_launch(void* const* d_in, const int* in_sizes, int n_in,
                              void* d_out, int out_size)
{
    const float* x    = (const float*)d_in[0];   // [2048*4096] fp32
    const float* grid = (const float*)d_in[1];   // [12] fp32
    const float* coef = (const float*)d_in[2];   // [8] fp32
    float* out = (float*)d_out;

    const int n  = in_sizes[0];
    const int n4 = n >> 2;

    int per_block = THREADS * VPT;
    int blocks = (n4 + per_block - 1) / per_block;
    if (blocks < 1) blocks = 1;

    bspline_act_kernel<<<blocks, THREADS>>>(x, grid, coef, out, n4);

    const int rem = n & 3;
    if (rem) {
        bspline_tail_kernel<<<1, 4>>>(x, grid, coef, out, n4 << 2, n);
    }
}